// round 16
// baseline (speedup 1.0000x reference)
#include <cuda_runtime.h>
#include <cuda_bf16.h>
#include <cstdint>

#define BATCH 16384
#define DIM   1024
#define DIM4  (DIM / 4)       // 256 float4 (=double2) per row
#define NL    4

__device__ float g_D[NL];     // D_l = dot(c_l, W_l), c_l = sum_{j<l} b_j
__device__ float g_Csum[DIM]; // b0+b1+b2+b3

// ---------------------------------------------------------------------------
// Precompute: 1 CTA, 1024 threads, reads 32 KB.
// ---------------------------------------------------------------------------
__global__ __launch_bounds__(DIM) void crossnet_precompute(
    const float* __restrict__ W, const float* __restrict__ b)
{
    int d = threadIdx.x;
    float b0 = b[d];
    float b1 = b[DIM + d];
    float b2 = b[2 * DIM + d];
    float b3 = b[3 * DIM + d];

    float c1 = b0;
    float c2 = c1 + b1;
    float c3 = c2 + b2;
    g_Csum[d] = c3 + b3;

    float p1 = c1 * W[DIM + d];
    float p2 = c2 * W[2 * DIM + d];
    float p3 = c3 * W[3 * DIM + d];

    #pragma unroll
    for (int o = 16; o; o >>= 1) {
        p1 += __shfl_xor_sync(0xFFFFFFFFu, p1, o);
        p2 += __shfl_xor_sync(0xFFFFFFFFu, p2, o);
        p3 += __shfl_xor_sync(0xFFFFFFFFu, p3, o);
    }
    __shared__ float sm[3][32];
    int warp = threadIdx.x >> 5;
    int lane = threadIdx.x & 31;
    if (lane == 0) { sm[0][warp] = p1; sm[1][warp] = p2; sm[2][warp] = p3; }
    __syncthreads();
    if (warp == 0) {
        float q1 = sm[0][lane];
        float q2 = sm[1][lane];
        float q3 = sm[2][lane];
        #pragma unroll
        for (int o = 16; o; o >>= 1) {
            q1 += __shfl_xor_sync(0xFFFFFFFFu, q1, o);
            q2 += __shfl_xor_sync(0xFFFFFFFFu, q2, o);
            q3 += __shfl_xor_sync(0xFFFFFFFFu, q3, o);
        }
        if (lane == 0) {
            g_D[0] = 0.0f; g_D[1] = q1; g_D[2] = q2; g_D[3] = q3;
        }
    }
}

// ---------------------------------------------------------------------------
// f32x2 packed helpers (sm_100a): one instruction = two fp32 FMAs.
// ---------------------------------------------------------------------------
typedef unsigned long long u64;
struct u64x2 { u64 x, y; };

__device__ __forceinline__ u64 ffma2(u64 a, u64 b, u64 c) {
    u64 d;
    asm("fma.rn.f32x2 %0, %1, %2, %3;" : "=l"(d) : "l"(a), "l"(b), "l"(c));
    return d;
}
__device__ __forceinline__ float hsum2(u64 p) {
    float2 v;
    asm("mov.b64 {%0, %1}, %2;" : "=f"(v.x), "=f"(v.y) : "l"(p));
    return v.x + v.y;
}
__device__ __forceinline__ u64 pack2(float lo, float hi) {
    u64 d;
    asm("mov.b64 %0, {%1, %2};" : "=l"(d) : "f"(lo), "f"(hi));
    return d;
}
__device__ __forceinline__ u64x2 as_u64x2(double2 v) {
    u64x2 r;
    r.x = __double_as_longlong(v.x);
    r.y = __double_as_longlong(v.y);
    return r;
}
__device__ __forceinline__ double2 as_double2(u64x2 v) {
    double2 r;
    r.x = __longlong_as_double(v.x);
    r.y = __longlong_as_double(v.y);
    return r;
}

// ---------------------------------------------------------------------------
// Main kernel: R13 structure (3 rows/warp, 24-deep front-batched LDG stream,
// W + Csum in shared, 2 CTAs/SM, f32x2 math), with the x0 miss batch issued
// BEFORE the W smem fill so fill+barrier hide under the miss latency.
// ---------------------------------------------------------------------------
#define TPB 256
#define WARPS_PER_CTA 8
#define ROWS_PER_WARP 3
#define ROWS_PER_CTA (WARPS_PER_CTA * ROWS_PER_WARP)             // 24
#define GRID ((BATCH + ROWS_PER_CTA - 1) / ROWS_PER_CTA)         // 683

__global__ __launch_bounds__(TPB, 2) void crossnet_main(
    const double2* __restrict__ x0,
    const double2* __restrict__ W4,
    double2* __restrict__ out)
{
    __shared__ double2 sW[NL][DIM4];   // 16 KB
    __shared__ double2 sC[DIM4];       //  4 KB
    __shared__ float   sD[NL];

    const int tid  = threadIdx.x;
    const int warp = tid >> 5;
    const int lane = tid & 31;

    // tiny fills first (L2-hot, 1 LDG.128 + scalars)
    sC[tid] = ((const double2*)g_Csum)[tid];
    if (tid < NL) sD[tid] = g_D[tid];

    const int base = blockIdx.x * ROWS_PER_CTA + warp * ROWS_PER_WARP;
    const int rA = min(base,     BATCH - 1);
    const int rB = min(base + 1, BATCH - 1);
    const int rC = min(base + 2, BATCH - 1);

    const double2* __restrict__ xa = x0 + (size_t)rA * DIM4;
    const double2* __restrict__ xb = x0 + (size_t)rB * DIM4;
    const double2* __restrict__ xc = x0 + (size_t)rC * DIM4;

    // ---- front-batch all 24 x loads FIRST (DRAM-miss stream) ----
    u64x2 xA[8], xB[8], xC[8];
    #pragma unroll
    for (int k = 0; k < 8; k++) {
        const int i = k * 32 + lane;
        xA[k] = as_u64x2(xa[i]);
        xB[k] = as_u64x2(xb[i]);
        xC[k] = as_u64x2(xc[i]);
    }

    // ---- W smem fill + barrier execute under the x-miss shadow ----
    sW[0][tid] = W4[tid];
    sW[1][tid] = W4[DIM4 + tid];
    sW[2][tid] = W4[2 * DIM4 + tid];
    sW[3][tid] = W4[3 * DIM4 + tid];
    __syncthreads();

    // ---- 12 packed dot products vs smem W ----
    u64 pA0 = 0, pA1 = 0, pA2 = 0, pA3 = 0;
    u64 pB0 = 0, pB1 = 0, pB2 = 0, pB3 = 0;
    u64 pC0 = 0, pC1 = 0, pC2 = 0, pC3 = 0;
    #pragma unroll
    for (int k = 0; k < 8; k++) {
        const int i = k * 32 + lane;
        u64x2 w0 = as_u64x2(sW[0][i]);
        u64x2 w1 = as_u64x2(sW[1][i]);
        u64x2 w2 = as_u64x2(sW[2][i]);
        u64x2 w3 = as_u64x2(sW[3][i]);
        pA0 = ffma2(xA[k].x, w0.x, pA0); pA0 = ffma2(xA[k].y, w0.y, pA0);
        pB0 = ffma2(xB[k].x, w0.x, pB0); pB0 = ffma2(xB[k].y, w0.y, pB0);
        pC0 = ffma2(xC[k].x, w0.x, pC0); pC0 = ffma2(xC[k].y, w0.y, pC0);
        pA1 = ffma2(xA[k].x, w1.x, pA1); pA1 = ffma2(xA[k].y, w1.y, pA1);
        pB1 = ffma2(xB[k].x, w1.x, pB1); pB1 = ffma2(xB[k].y, w1.y, pB1);
        pC1 = ffma2(xC[k].x, w1.x, pC1); pC1 = ffma2(xC[k].y, w1.y, pC1);
        pA2 = ffma2(xA[k].x, w2.x, pA2); pA2 = ffma2(xA[k].y, w2.y, pA2);
        pB2 = ffma2(xB[k].x, w2.x, pB2); pB2 = ffma2(xB[k].y, w2.y, pB2);
        pC2 = ffma2(xC[k].x, w2.x, pC2); pC2 = ffma2(xC[k].y, w2.y, pC2);
        pA3 = ffma2(xA[k].x, w3.x, pA3); pA3 = ffma2(xA[k].y, w3.y, pA3);
        pB3 = ffma2(xB[k].x, w3.x, pB3); pB3 = ffma2(xB[k].y, w3.y, pB3);
        pC3 = ffma2(xC[k].x, w3.x, pC3); pC3 = ffma2(xC[k].y, w3.y, pC3);
    }

    // collapse packed pairs to scalars, then shuffle-reduce
    float uA0 = hsum2(pA0), uA1 = hsum2(pA1), uA2 = hsum2(pA2), uA3 = hsum2(pA3);
    float uB0 = hsum2(pB0), uB1 = hsum2(pB1), uB2 = hsum2(pB2), uB3 = hsum2(pB3);
    float uC0 = hsum2(pC0), uC1 = hsum2(pC1), uC2 = hsum2(pC2), uC3 = hsum2(pC3);

    #pragma unroll
    for (int o = 16; o; o >>= 1) {
        uA0 += __shfl_xor_sync(0xFFFFFFFFu, uA0, o);
        uA1 += __shfl_xor_sync(0xFFFFFFFFu, uA1, o);
        uA2 += __shfl_xor_sync(0xFFFFFFFFu, uA2, o);
        uA3 += __shfl_xor_sync(0xFFFFFFFFu, uA3, o);
        uB0 += __shfl_xor_sync(0xFFFFFFFFu, uB0, o);
        uB1 += __shfl_xor_sync(0xFFFFFFFFu, uB1, o);
        uB2 += __shfl_xor_sync(0xFFFFFFFFu, uB2, o);
        uB3 += __shfl_xor_sync(0xFFFFFFFFu, uB3, o);
        uC0 += __shfl_xor_sync(0xFFFFFFFFu, uC0, o);
        uC1 += __shfl_xor_sync(0xFFFFFFFFu, uC1, o);
        uC2 += __shfl_xor_sync(0xFFFFFFFFu, uC2, o);
        uC3 += __shfl_xor_sync(0xFFFFFFFFu, uC3, o);
    }

    const float D1 = sD[1], D2 = sD[2], D3 = sD[3];

    float aA = 1.0f + uA0;                 // D0 == 0
    aA += fmaf(aA, uA1, D1);
    aA += fmaf(aA, uA2, D2);
    aA += fmaf(aA, uA3, D3);

    float aB = 1.0f + uB0;
    aB += fmaf(aB, uB1, D1);
    aB += fmaf(aB, uB2, D2);
    aB += fmaf(aB, uB3, D3);

    float aC = 1.0f + uC0;
    aC += fmaf(aC, uC1, D1);
    aC += fmaf(aC, uC2, D2);
    aC += fmaf(aC, uC3, D3);

    const u64 aA2 = pack2(aA, aA);
    const u64 aB2 = pack2(aB, aB);
    const u64 aC2 = pack2(aC, aC);

    // ---- write: out = a * x0 + Csum (packed), streaming stores ----
    double2* __restrict__ oa = out + (size_t)rA * DIM4;
    double2* __restrict__ ob = out + (size_t)rB * DIM4;
    double2* __restrict__ oc = out + (size_t)rC * DIM4;

    #pragma unroll
    for (int k = 0; k < 8; k++) {
        const int i = k * 32 + lane;
        u64x2 c = as_u64x2(sC[i]);
        u64x2 rA4, rB4, rC4;
        rA4.x = ffma2(aA2, xA[k].x, c.x); rA4.y = ffma2(aA2, xA[k].y, c.y);
        rB4.x = ffma2(aB2, xB[k].x, c.x); rB4.y = ffma2(aB2, xB[k].y, c.y);
        rC4.x = ffma2(aC2, xC[k].x, c.x); rC4.y = ffma2(aC2, xC[k].y, c.y);
        __stcs(&oa[i], as_double2(rA4));
        __stcs(&ob[i], as_double2(rB4));
        __stcs(&oc[i], as_double2(rC4));
    }
}

extern "C" void kernel_launch(void* const* d_in, const int* in_sizes, int n_in,
                              void* d_out, int out_size)
{
    const float* x0 = (const float*)d_in[0];   // [16384, 1024]
    const float* W  = (const float*)d_in[1];   // [4, 1024]
    const float* b  = (const float*)d_in[2];   // [4, 1024]
    float* out      = (float*)d_out;           // [16384, 1024]

    crossnet_precompute<<<1, DIM>>>(W, b);
    crossnet_main<<<GRID, TPB>>>((const double2*)x0, (const double2*)W,
                                 (double2*)out);
}

// round 17
// speedup vs baseline: 1.5058x; 1.5058x over previous
#include <cuda_runtime.h>
#include <cuda_bf16.h>
#include <cstdint>

#define BATCH 16384
#define DIM   1024
#define DIM4  (DIM / 4)       // 256 float4 (=double2) per row
#define NL    4

__device__ float g_D[NL];     // D_l = dot(c_l, W_l), c_l = sum_{j<l} b_j
__device__ float g_Csum[DIM]; // b0+b1+b2+b3

// ---------------------------------------------------------------------------
// Precompute: 1 CTA, 1024 threads, reads 32 KB.
// ---------------------------------------------------------------------------
__global__ __launch_bounds__(DIM) void crossnet_precompute(
    const float* __restrict__ W, const float* __restrict__ b)
{
    int d = threadIdx.x;
    float b0 = b[d];
    float b1 = b[DIM + d];
    float b2 = b[2 * DIM + d];
    float b3 = b[3 * DIM + d];

    float c1 = b0;
    float c2 = c1 + b1;
    float c3 = c2 + b2;
    g_Csum[d] = c3 + b3;

    float p1 = c1 * W[DIM + d];
    float p2 = c2 * W[2 * DIM + d];
    float p3 = c3 * W[3 * DIM + d];

    #pragma unroll
    for (int o = 16; o; o >>= 1) {
        p1 += __shfl_xor_sync(0xFFFFFFFFu, p1, o);
        p2 += __shfl_xor_sync(0xFFFFFFFFu, p2, o);
        p3 += __shfl_xor_sync(0xFFFFFFFFu, p3, o);
    }
    __shared__ float sm[3][32];
    int warp = threadIdx.x >> 5;
    int lane = threadIdx.x & 31;
    if (lane == 0) { sm[0][warp] = p1; sm[1][warp] = p2; sm[2][warp] = p3; }
    __syncthreads();
    if (warp == 0) {
        float q1 = sm[0][lane];
        float q2 = sm[1][lane];
        float q3 = sm[2][lane];
        #pragma unroll
        for (int o = 16; o; o >>= 1) {
            q1 += __shfl_xor_sync(0xFFFFFFFFu, q1, o);
            q2 += __shfl_xor_sync(0xFFFFFFFFu, q2, o);
            q3 += __shfl_xor_sync(0xFFFFFFFFu, q3, o);
        }
        if (lane == 0) {
            g_D[0] = 0.0f; g_D[1] = q1; g_D[2] = q2; g_D[3] = q3;
        }
    }
}

// ---------------------------------------------------------------------------
// f32x2 packed helpers (sm_100a): one instruction = two fp32 FMAs.
// ---------------------------------------------------------------------------
typedef unsigned long long u64;
struct u64x2 { u64 x, y; };

__device__ __forceinline__ u64 ffma2(u64 a, u64 b, u64 c) {
    u64 d;
    asm("fma.rn.f32x2 %0, %1, %2, %3;" : "=l"(d) : "l"(a), "l"(b), "l"(c));
    return d;
}
__device__ __forceinline__ float hsum2(u64 p) {
    float2 v;
    asm("mov.b64 {%0, %1}, %2;" : "=f"(v.x), "=f"(v.y) : "l"(p));
    return v.x + v.y;
}
__device__ __forceinline__ u64 pack2(float lo, float hi) {
    u64 d;
    asm("mov.b64 %0, {%1, %2};" : "=l"(d) : "f"(lo), "f"(hi));
    return d;
}
__device__ __forceinline__ u64x2 as_u64x2(double2 v) {
    u64x2 r;
    r.x = __double_as_longlong(v.x);
    r.y = __double_as_longlong(v.y);
    return r;
}
__device__ __forceinline__ double2 as_double2(u64x2 v) {
    double2 r;
    r.x = __longlong_as_double(v.x);
    r.y = __longlong_as_double(v.y);
    return r;
}

// ---------------------------------------------------------------------------
// Main kernel (R13, converged best): 3 rows/warp, 24-deep front-batched LDG
// stream, W + Csum in shared (filled FIRST — short loads must precede the
// deep miss batch in the L1tex FIFO), 2 CTAs/SM, f32x2 packed math,
// streaming stores.
// ---------------------------------------------------------------------------
#define TPB 256
#define WARPS_PER_CTA 8
#define ROWS_PER_WARP 3
#define ROWS_PER_CTA (WARPS_PER_CTA * ROWS_PER_WARP)             // 24
#define GRID ((BATCH + ROWS_PER_CTA - 1) / ROWS_PER_CTA)         // 683

__global__ __launch_bounds__(TPB, 2) void crossnet_main(
    const double2* __restrict__ x0,
    const double2* __restrict__ W4,
    double2* __restrict__ out)
{
    __shared__ double2 sW[NL][DIM4];   // 16 KB
    __shared__ double2 sC[DIM4];       //  4 KB
    __shared__ float   sD[NL];

    const int tid  = threadIdx.x;
    const int warp = tid >> 5;
    const int lane = tid & 31;

    // one-time smem fill (DIM4 == TPB) — BEFORE the miss batch (FIFO order)
    sW[0][tid] = W4[tid];
    sW[1][tid] = W4[DIM4 + tid];
    sW[2][tid] = W4[2 * DIM4 + tid];
    sW[3][tid] = W4[3 * DIM4 + tid];
    sC[tid]    = ((const double2*)g_Csum)[tid];
    if (tid < NL) sD[tid] = g_D[tid];
    __syncthreads();

    const int base = blockIdx.x * ROWS_PER_CTA + warp * ROWS_PER_WARP;
    const int rA = min(base,     BATCH - 1);
    const int rB = min(base + 1, BATCH - 1);
    const int rC = min(base + 2, BATCH - 1);

    const double2* __restrict__ xa = x0 + (size_t)rA * DIM4;
    const double2* __restrict__ xb = x0 + (size_t)rB * DIM4;
    const double2* __restrict__ xc = x0 + (size_t)rC * DIM4;

    // ---- front-batch all 24 x loads (DRAM-miss stream) ----
    u64x2 xA[8], xB[8], xC[8];
    #pragma unroll
    for (int k = 0; k < 8; k++) {
        const int i = k * 32 + lane;
        xA[k] = as_u64x2(xa[i]);
        xB[k] = as_u64x2(xb[i]);
        xC[k] = as_u64x2(xc[i]);
    }

    // ---- 12 packed dot products vs smem W ----
    u64 pA0 = 0, pA1 = 0, pA2 = 0, pA3 = 0;
    u64 pB0 = 0, pB1 = 0, pB2 = 0, pB3 = 0;
    u64 pC0 = 0, pC1 = 0, pC2 = 0, pC3 = 0;
    #pragma unroll
    for (int k = 0; k < 8; k++) {
        const int i = k * 32 + lane;
        u64x2 w0 = as_u64x2(sW[0][i]);
        u64x2 w1 = as_u64x2(sW[1][i]);
        u64x2 w2 = as_u64x2(sW[2][i]);
        u64x2 w3 = as_u64x2(sW[3][i]);
        pA0 = ffma2(xA[k].x, w0.x, pA0); pA0 = ffma2(xA[k].y, w0.y, pA0);
        pB0 = ffma2(xB[k].x, w0.x, pB0); pB0 = ffma2(xB[k].y, w0.y, pB0);
        pC0 = ffma2(xC[k].x, w0.x, pC0); pC0 = ffma2(xC[k].y, w0.y, pC0);
        pA1 = ffma2(xA[k].x, w1.x, pA1); pA1 = ffma2(xA[k].y, w1.y, pA1);
        pB1 = ffma2(xB[k].x, w1.x, pB1); pB1 = ffma2(xB[k].y, w1.y, pB1);
        pC1 = ffma2(xC[k].x, w1.x, pC1); pC1 = ffma2(xC[k].y, w1.y, pC1);
        pA2 = ffma2(xA[k].x, w2.x, pA2); pA2 = ffma2(xA[k].y, w2.y, pA2);
        pB2 = ffma2(xB[k].x, w2.x, pB2); pB2 = ffma2(xB[k].y, w2.y, pB2);
        pC2 = ffma2(xC[k].x, w2.x, pC2); pC2 = ffma2(xC[k].y, w2.y, pC2);
        pA3 = ffma2(xA[k].x, w3.x, pA3); pA3 = ffma2(xA[k].y, w3.y, pA3);
        pB3 = ffma2(xB[k].x, w3.x, pB3); pB3 = ffma2(xB[k].y, w3.y, pB3);
        pC3 = ffma2(xC[k].x, w3.x, pC3); pC3 = ffma2(xC[k].y, w3.y, pC3);
    }

    // collapse packed pairs to scalars
    float uA0 = hsum2(pA0), uA1 = hsum2(pA1), uA2 = hsum2(pA2), uA3 = hsum2(pA3);
    float uB0 = hsum2(pB0), uB1 = hsum2(pB1), uB2 = hsum2(pB2), uB3 = hsum2(pB3);
    float uC0 = hsum2(pC0), uC1 = hsum2(pC1), uC2 = hsum2(pC2), uC3 = hsum2(pC3);

    #pragma unroll
    for (int o = 16; o; o >>= 1) {
        uA0 += __shfl_xor_sync(0xFFFFFFFFu, uA0, o);
        uA1 += __shfl_xor_sync(0xFFFFFFFFu, uA1, o);
        uA2 += __shfl_xor_sync(0xFFFFFFFFu, uA2, o);
        uA3 += __shfl_xor_sync(0xFFFFFFFFu, uA3, o);
        uB0 += __shfl_xor_sync(0xFFFFFFFFu, uB0, o);
        uB1 += __shfl_xor_sync(0xFFFFFFFFu, uB1, o);
        uB2 += __shfl_xor_sync(0xFFFFFFFFu, uB2, o);
        uB3 += __shfl_xor_sync(0xFFFFFFFFu, uB3, o);
        uC0 += __shfl_xor_sync(0xFFFFFFFFu, uC0, o);
        uC1 += __shfl_xor_sync(0xFFFFFFFFu, uC1, o);
        uC2 += __shfl_xor_sync(0xFFFFFFFFu, uC2, o);
        uC3 += __shfl_xor_sync(0xFFFFFFFFu, uC3, o);
    }

    const float D1 = sD[1], D2 = sD[2], D3 = sD[3];

    float aA = 1.0f + uA0;                 // D0 == 0
    aA += fmaf(aA, uA1, D1);
    aA += fmaf(aA, uA2, D2);
    aA += fmaf(aA, uA3, D3);

    float aB = 1.0f + uB0;
    aB += fmaf(aB, uB1, D1);
    aB += fmaf(aB, uB2, D2);
    aB += fmaf(aB, uB3, D3);

    float aC = 1.0f + uC0;
    aC += fmaf(aC, uC1, D1);
    aC += fmaf(aC, uC2, D2);
    aC += fmaf(aC, uC3, D3);

    const u64 aA2 = pack2(aA, aA);
    const u64 aB2 = pack2(aB, aB);
    const u64 aC2 = pack2(aC, aC);

    // ---- write: out = a * x0 + Csum (packed), streaming stores ----
    double2* __restrict__ oa = out + (size_t)rA * DIM4;
    double2* __restrict__ ob = out + (size_t)rB * DIM4;
    double2* __restrict__ oc = out + (size_t)rC * DIM4;

    #pragma unroll
    for (int k = 0; k < 8; k++) {
        const int i = k * 32 + lane;
        u64x2 c = as_u64x2(sC[i]);
        u64x2 rA4, rB4, rC4;
        rA4.x = ffma2(aA2, xA[k].x, c.x); rA4.y = ffma2(aA2, xA[k].y, c.y);
        rB4.x = ffma2(aB2, xB[k].x, c.x); rB4.y = ffma2(aB2, xB[k].y, c.y);
        rC4.x = ffma2(aC2, xC[k].x, c.x); rC4.y = ffma2(aC2, xC[k].y, c.y);
        __stcs(&oa[i], as_double2(rA4));
        __stcs(&ob[i], as_double2(rB4));
        __stcs(&oc[i], as_double2(rC4));
    }
}

extern "C" void kernel_launch(void* const* d_in, const int* in_sizes, int n_in,
                              void* d_out, int out_size)
{
    const float* x0 = (const float*)d_in[0];   // [16384, 1024]
    const float* W  = (const float*)d_in[1];   // [4, 1024]
    const float* b  = (const float*)d_in[2];   // [4, 1024]
    float* out      = (float*)d_out;           // [16384, 1024]

    crossnet_precompute<<<1, DIM>>>(W, b);
    crossnet_main<<<GRID, TPB>>>((const double2*)x0, (const double2*)W,
                                 (double2*)out);
}